// round 1
// baseline (speedup 1.0000x reference)
#include <cuda_runtime.h>
#include <math.h>
#include <stdint.h>

#define DIM 768
#define TOPK 5
#define COS_EPS 1e-8f
#define W_EPS 1e-6f
#define MAXN 500000

// Scratch (device globals: allocation-free per harness rules)
__device__ float g_dist[MAXN];
__device__ float g_qn;
__device__ float g_topdist[TOPK];
__device__ int   g_topidx[TOPK];

// Monotone float->uint mapping (handles negative just in case)
__device__ __forceinline__ unsigned int f2u_mono(float f) {
    unsigned int b = __float_as_uint(f);
    return b ^ ((unsigned int)(((int)b) >> 31) | 0x80000000u);
}
__device__ __forceinline__ float u2f_mono(unsigned int u) {
    unsigned int b = (u & 0x80000000u) ? (u ^ 0x80000000u) : ~u;
    return __uint_as_float(b);
}

// ---------------- kernel 0: query norm ----------------
__global__ void qnorm_kernel(const float* __restrict__ q) {
    __shared__ float red[32];
    float s = 0.f;
    for (int i = threadIdx.x; i < DIM; i += blockDim.x) {
        float v = q[i];
        s += v * v;
    }
    for (int o = 16; o; o >>= 1) s += __shfl_xor_sync(0xFFFFFFFFu, s, o);
    if ((threadIdx.x & 31) == 0) red[threadIdx.x >> 5] = s;
    __syncthreads();
    if (threadIdx.x < 32) {
        int nw = (blockDim.x + 31) >> 5;
        float v = (threadIdx.x < nw) ? red[threadIdx.x] : 0.f;
        for (int o = 16; o; o >>= 1) v += __shfl_xor_sync(0xFFFFFFFFu, v, o);
        if (threadIdx.x == 0) g_qn = fmaxf(sqrtf(v), COS_EPS);
    }
}

// ---------------- kernel 1: per-row cosine distance ----------------
// One warp per row; float4 loads -> 512B contiguous per warp iteration.
__global__ void dist_kernel(const float* __restrict__ db,
                            const float* __restrict__ q, int n) {
    __shared__ __align__(16) float sq[DIM];
    for (int i = threadIdx.x; i < DIM; i += blockDim.x) sq[i] = q[i];
    __syncthreads();
    const float qn = g_qn;

    const int lane  = threadIdx.x & 31;
    const int warp  = (blockIdx.x * blockDim.x + threadIdx.x) >> 5;
    const int nwarp = (gridDim.x * blockDim.x) >> 5;
    const float4* qv4 = (const float4*)sq;

    for (int row = warp; row < n; row += nwarp) {
        const float4* r = (const float4*)(db + (size_t)row * DIM);
        float dot = 0.f, nrm = 0.f;
        #pragma unroll
        for (int j = 0; j < DIM / (32 * 4); j++) {
            float4 v  = r[lane + 32 * j];
            float4 qv = qv4[lane + 32 * j];
            dot += v.x * qv.x + v.y * qv.y + v.z * qv.z + v.w * qv.w;
            nrm += v.x * v.x + v.y * v.y + v.z * v.z + v.w * v.w;
        }
        #pragma unroll
        for (int o = 16; o; o >>= 1) {
            dot += __shfl_xor_sync(0xFFFFFFFFu, dot, o);
            nrm += __shfl_xor_sync(0xFFFFFFFFu, nrm, o);
        }
        if (lane == 0) {
            float dn = fmaxf(sqrtf(nrm), COS_EPS);
            g_dist[row] = 1.f - dot / (dn * qn);
        }
    }
}

// ---------------- kernel 2: top-5 (smallest distance) ----------------
// Single block, 5 sequential argmin passes; dist array is L2-hot.
__global__ void topk_kernel(int n) {
    __shared__ unsigned long long red[32];
    __shared__ unsigned long long sel[TOPK];
    const int tid = threadIdx.x;
    const int nthr = blockDim.x;

    for (int k = 0; k < TOPK; k++) {
        unsigned long long best = ~0ULL;
        for (int i = tid; i < n; i += nthr) {
            unsigned long long key =
                ((unsigned long long)f2u_mono(g_dist[i]) << 32) | (unsigned int)i;
            bool taken = false;
            #pragma unroll
            for (int j = 0; j < TOPK; j++)
                if (j < k && sel[j] == key) taken = true;
            if (!taken && key < best) best = key;
        }
        // block min-reduce
        #pragma unroll
        for (int o = 16; o; o >>= 1) {
            unsigned long long other = __shfl_xor_sync(0xFFFFFFFFu, best, o);
            if (other < best) best = other;
        }
        if ((tid & 31) == 0) red[tid >> 5] = best;
        __syncthreads();
        if (tid < 32) {
            int nw = (nthr + 31) >> 5;
            unsigned long long v = (tid < nw) ? red[tid] : ~0ULL;
            #pragma unroll
            for (int o = 16; o; o >>= 1) {
                unsigned long long other = __shfl_xor_sync(0xFFFFFFFFu, v, o);
                if (other < v) v = other;
            }
            if (tid == 0) {
                sel[k] = v;
                g_topdist[k] = u2f_mono((unsigned int)(v >> 32));
                g_topidx[k]  = (int)(unsigned int)(v & 0xFFFFFFFFu);
            }
        }
        __syncthreads();
    }
}

// ---------------- kernel 3: weighted centroid ----------------
__global__ void centroid_kernel(const float* __restrict__ db,
                                float* __restrict__ out) {
    __shared__ float w[TOPK];
    __shared__ int   id[TOPK];
    if (threadIdx.x == 0) {
        float raw[TOPK], s = 0.f;
        #pragma unroll
        for (int k = 0; k < TOPK; k++) {
            float d = g_topdist[k] + W_EPS;
            raw[k] = 1.f / (d * d);
            s += raw[k];
            id[k] = g_topidx[k];
        }
        #pragma unroll
        for (int k = 0; k < TOPK; k++) w[k] = raw[k] / s;
    }
    __syncthreads();
    int j = threadIdx.x;
    if (j < DIM) {
        float acc = 0.f;
        #pragma unroll
        for (int k = 0; k < TOPK; k++)
            acc += w[k] * db[(size_t)id[k] * DIM + j];
        out[j] = acc;
    }
}

extern "C" void kernel_launch(void* const* d_in, const int* in_sizes, int n_in,
                              void* d_out, int out_size) {
    const float* q  = (const float*)d_in[0];
    const float* db = (const float*)d_in[1];
    float* out = (float*)d_out;
    const int n = in_sizes[1] / DIM;

    qnorm_kernel<<<1, 256>>>(q);

    // grid-stride, one warp per row; ~32 warps/SM * 148 SMs of parallelism
    int blocks = 4736;  // 148 * 32, 256 thr = 8 warps each
    dist_kernel<<<blocks, 256>>>(db, q, n);

    topk_kernel<<<1, 1024>>>(n);

    centroid_kernel<<<1, DIM>>>(db, out);
}

// round 2
// speedup vs baseline: 4.0356x; 4.0356x over previous
#include <cuda_runtime.h>
#include <math.h>
#include <stdint.h>

#define DIM 768
#define TOPK 5
#define COS_EPS 1e-8f
#define W_EPS 1e-6f

#define NBLOCKS 1184      // 148 SMs * 8 blocks (one full wave at 256 thr)
#define NTHREADS 256      // 8 warps
#define NWARPS_TOTAL (NBLOCKS * (NTHREADS / 32))
#define NCAND (NBLOCKS * TOPK)

// candidate keys: (monotone dist bits << 32) | row index
__device__ unsigned long long g_cand[NCAND];

__device__ __forceinline__ unsigned int f2u_mono(float f) {
    unsigned int b = __float_as_uint(f);
    return b ^ ((unsigned int)(((int)b) >> 31) | 0x80000000u);
}
__device__ __forceinline__ float u2f_mono(unsigned int u) {
    unsigned int b = (u & 0x80000000u) ? (u ^ 0x80000000u) : ~u;
    return __uint_as_float(b);
}

__device__ __forceinline__ void insert5(unsigned long long best[TOPK],
                                        unsigned long long key) {
    if (key < best[TOPK - 1]) {
        best[TOPK - 1] = key;
        #pragma unroll
        for (int k = TOPK - 1; k > 0; k--) {
            if (best[k] < best[k - 1]) {
                unsigned long long t = best[k];
                best[k] = best[k - 1];
                best[k - 1] = t;
            }
        }
    }
}

// ---------------- kernel 1: fused cosine-distance + per-block top-5 ----------------
__global__ void __launch_bounds__(NTHREADS)
dist_topk_kernel(const float* __restrict__ db, const float* __restrict__ q, int n) {
    __shared__ __align__(16) float sq[DIM];
    __shared__ float s_wss[NTHREADS / 32];
    __shared__ float s_qn;
    __shared__ unsigned long long s_cand[(NTHREADS / 32) * TOPK];

    const int tid  = threadIdx.x;
    const int lane = tid & 31;
    const int wid  = tid >> 5;

    // load query into shared + compute query norm (redundantly per block; cheap)
    float ss = 0.f;
    for (int i = tid; i < DIM; i += NTHREADS) {
        float v = q[i];
        sq[i] = v;
        ss += v * v;
    }
    #pragma unroll
    for (int o = 16; o; o >>= 1) ss += __shfl_xor_sync(0xFFFFFFFFu, ss, o);
    if (lane == 0) s_wss[wid] = ss;
    __syncthreads();
    if (tid == 0) {
        float t = 0.f;
        #pragma unroll
        for (int i = 0; i < NTHREADS / 32; i++) t += s_wss[i];
        s_qn = fmaxf(sqrtf(t), COS_EPS);
    }
    __syncthreads();
    const float qn = s_qn;
    const float4* qv4 = (const float4*)sq;

    // contiguous row range for this warp (single wave, page/L2 locality)
    const int gwarp = blockIdx.x * (NTHREADS / 32) + wid;
    const int rpw = (n + NWARPS_TOTAL - 1) / NWARPS_TOTAL;
    const int start = gwarp * rpw;
    const int end = min(start + rpw, n);

    unsigned long long best[TOPK];
    #pragma unroll
    for (int k = 0; k < TOPK; k++) best[k] = ~0ULL;

    for (int row = start; row < end; row += 2) {
        const bool two = (row + 1 < end);
        const float4* r0 = (const float4*)(db + (size_t)row * DIM);
        const float4* r1 = two ? (const float4*)(db + (size_t)(row + 1) * DIM) : r0;

        float dot0 = 0.f, nrm0 = 0.f, dot1 = 0.f, nrm1 = 0.f;
        #pragma unroll
        for (int j = 0; j < DIM / (32 * 4); j++) {
            float4 a = __ldcs(&r0[lane + 32 * j]);
            float4 b = __ldcs(&r1[lane + 32 * j]);
            float4 qv = qv4[lane + 32 * j];
            dot0 += a.x * qv.x + a.y * qv.y + a.z * qv.z + a.w * qv.w;
            nrm0 += a.x * a.x + a.y * a.y + a.z * a.z + a.w * a.w;
            dot1 += b.x * qv.x + b.y * qv.y + b.z * qv.z + b.w * qv.w;
            nrm1 += b.x * b.x + b.y * b.y + b.z * b.z + b.w * b.w;
        }
        #pragma unroll
        for (int o = 16; o; o >>= 1) {
            dot0 += __shfl_xor_sync(0xFFFFFFFFu, dot0, o);
            nrm0 += __shfl_xor_sync(0xFFFFFFFFu, nrm0, o);
            dot1 += __shfl_xor_sync(0xFFFFFFFFu, dot1, o);
            nrm1 += __shfl_xor_sync(0xFFFFFFFFu, nrm1, o);
        }
        if (lane == 0) {
            float d0 = 1.f - dot0 / (fmaxf(sqrtf(nrm0), COS_EPS) * qn);
            insert5(best, ((unsigned long long)f2u_mono(d0) << 32) | (unsigned int)row);
            if (two) {
                float d1 = 1.f - dot1 / (fmaxf(sqrtf(nrm1), COS_EPS) * qn);
                insert5(best, ((unsigned long long)f2u_mono(d1) << 32) | (unsigned int)(row + 1));
            }
        }
    }

    // block merge: 8 warps * 5 keys -> 5 keys
    if (lane == 0) {
        #pragma unroll
        for (int k = 0; k < TOPK; k++) s_cand[wid * TOPK + k] = best[k];
    }
    __syncthreads();
    if (tid == 0) {
        const int m = (NTHREADS / 32) * TOPK;  // 40
        #pragma unroll
        for (int k = 0; k < TOPK; k++) {
            unsigned long long mn = ~0ULL;
            int mi = 0;
            for (int i = 0; i < m; i++) {
                unsigned long long v = s_cand[i];
                if (v < mn) { mn = v; mi = i; }
            }
            g_cand[blockIdx.x * TOPK + k] = mn;
            s_cand[mi] = ~0ULL;
        }
    }
}

// ---------------- kernel 2: global top-5 + weighted centroid ----------------
__global__ void __launch_bounds__(DIM)
finish_kernel(const float* __restrict__ db, float* __restrict__ out) {
    __shared__ unsigned long long red[32];
    __shared__ unsigned long long sel[TOPK];
    __shared__ float w[TOPK];
    __shared__ int   id[TOPK];

    const int tid = threadIdx.x;
    const int lane = tid & 31;
    const int wid = tid >> 5;
    const int nwarp = DIM / 32;  // 24

    for (int k = 0; k < TOPK; k++) {
        unsigned long long bst = ~0ULL;
        for (int i = tid; i < NCAND; i += DIM) {
            unsigned long long key = g_cand[i];
            bool taken = false;
            #pragma unroll
            for (int j = 0; j < TOPK; j++)
                if (j < k && sel[j] == key) taken = true;
            if (!taken && key < bst) bst = key;
        }
        #pragma unroll
        for (int o = 16; o; o >>= 1) {
            unsigned long long v = __shfl_xor_sync(0xFFFFFFFFu, bst, o);
            if (v < bst) bst = v;
        }
        if (lane == 0) red[wid] = bst;
        __syncthreads();
        if (tid < 32) {
            unsigned long long v = (tid < nwarp) ? red[tid] : ~0ULL;
            #pragma unroll
            for (int o = 16; o; o >>= 1) {
                unsigned long long u = __shfl_xor_sync(0xFFFFFFFFu, v, o);
                if (u < v) v = u;
            }
            if (tid == 0) sel[k] = v;
        }
        __syncthreads();
    }

    if (tid == 0) {
        float raw[TOPK], s = 0.f;
        #pragma unroll
        for (int k = 0; k < TOPK; k++) {
            float d = u2f_mono((unsigned int)(sel[k] >> 32)) + W_EPS;
            raw[k] = 1.f / (d * d);
            s += raw[k];
            id[k] = (int)(unsigned int)(sel[k] & 0xFFFFFFFFu);
        }
        #pragma unroll
        for (int k = 0; k < TOPK; k++) w[k] = raw[k] / s;
    }
    __syncthreads();

    float acc = 0.f;
    #pragma unroll
    for (int k = 0; k < TOPK; k++)
        acc += w[k] * db[(size_t)id[k] * DIM + tid];
    out[tid] = acc;
}

extern "C" void kernel_launch(void* const* d_in, const int* in_sizes, int n_in,
                              void* d_out, int out_size) {
    const float* q  = (const float*)d_in[0];
    const float* db = (const float*)d_in[1];
    float* out = (float*)d_out;
    const int n = in_sizes[1] / DIM;

    dist_topk_kernel<<<NBLOCKS, NTHREADS>>>(db, q, n);
    finish_kernel<<<1, DIM>>>(db, out);
}